// round 3
// baseline (speedup 1.0000x reference)
#include <cuda_runtime.h>
#include <math.h>

#define PADW 68
#define PLANE (PADW * PADW)   // 4624

__device__ float  g_xpad[256 * PLANE];
__device__ float  g_psum[256];
__device__ float  g_emb[4096];     // [c][f*16+p]
__device__ float4 g_geo[1024];     // [c*16+p] = (floor(Ax), floor(Ay), wx, wy)
__device__ float  g_Wc[8192];      // [p][k][c]
__device__ float  g_We[8192];      // [p][c][k]

// ---------------- K1: zero-pad copy + per-(b,c) plane sum ----------------
__global__ void k1_pad(const float* __restrict__ x) {
    int bc = blockIdx.x, tid = threadIdx.x;
    const float* src = x + bc * 4096;
    float* dst = g_xpad + bc * PLANE;
    float s = 0.f;
    for (int i = tid; i < PLANE; i += 256) {
        int r = i / PADW, cl = i - r * PADW;
        int rr = r - 2, cc = cl - 2;
        float v = 0.f;
        if ((unsigned)rr < 64u && (unsigned)cc < 64u) v = src[rr * 64 + cc];
        dst[i] = v;
        s += v;
    }
    __shared__ float red[8];
    for (int o = 16; o > 0; o >>= 1) s += __shfl_down_sync(0xffffffffu, s, o);
    if ((tid & 31) == 0) red[tid >> 5] = s;
    __syncthreads();
    if (tid < 8) {
        s = red[tid];
        for (int o = 4; o > 0; o >>= 1) s += __shfl_down_sync(0xffu, s, o);
        if (tid == 0) g_psum[bc] = s;
    }
}

// ---------------- K2: emb[c][fp] ----------------
__global__ void k2_emb(const float* __restrict__ Wb1, const float* __restrict__ bb1,
                       const float* __restrict__ Wb2, const float* __restrict__ bb2) {
    __shared__ float s_cm[64], s_S[128], s_t1[4096];
    int tid = threadIdx.x;
    if (tid < 64)
        s_cm[tid] = (g_psum[tid] + g_psum[64 + tid] + g_psum[128 + tid] + g_psum[192 + tid])
                    * (1.0f / 16384.0f);
    __syncthreads();
    if (tid < 64) {
        float s0 = 0.f, s1 = 0.f;
        const float* row = Wb1 + tid * 64;
        for (int j = 0; j < 64; j++) { float w = row[j]; s0 += w * s_cm[j]; s1 += w; }
        s_S[tid] = s0; s_S[64 + tid] = s1;
    }
    __syncthreads();
    for (int i = tid; i < 4096; i += 256) {
        int c = i >> 6, fp = i & 63, f = fp >> 4, p = fp & 15;
        float meta = (f == 0) ? 1.f : (f == 1) ? 0.25f
                   : (f == 2) ? ((float)(p >> 2) * 0.25f - 0.375f)
                              : ((float)(p & 3) * 0.25f - 0.375f);
        float base = (f == 0) ? s_S[c] : s_S[64 + c];
        s_t1[c * 64 + fp] = fmaxf(meta * base + bb1[c], 0.f);
    }
    __syncthreads();
    for (int i = tid; i < 4096; i += 256) {
        int o = i >> 6, fp = i & 63;
        float acc = bb2[o];
        const float* wr = Wb2 + o * 64;
        for (int c = 0; c < 64; c++) acc += wr[c] * s_t1[c * 64 + fp];
        g_emb[o * 64 + fp] = fmaxf(acc, 0.f);
    }
}

// ---------------- K3a: offset head, one warp per (c,p) task ----------------
__global__ void k3a_off(const float* __restrict__ Wo1, const float* __restrict__ bo1,
                        const float* __restrict__ Wo2, const float* __restrict__ bo2,
                        const float* __restrict__ Wo3, const float* __restrict__ bo3) {
    __shared__ float s_v1[8][64], s_v2[8][64];
    int wid = threadIdx.x >> 5, lane = threadIdx.x & 31;
    int task = blockIdx.x * 8 + wid;   // c*16+p
    int c = task >> 4, p = task & 15;
    float e0 = g_emb[c * 64 + p],      e1 = g_emb[c * 64 + 16 + p];
    float e2 = g_emb[c * 64 + 32 + p], e3 = g_emb[c * 64 + 48 + p];
    for (int r = 0; r < 2; r++) {
        int o = lane + r * 32;
        float v = bo1[o] + Wo1[o*4]*e0 + Wo1[o*4+1]*e1 + Wo1[o*4+2]*e2 + Wo1[o*4+3]*e3;
        s_v1[wid][o] = fmaxf(v, 0.f);
    }
    __syncwarp();
    for (int r = 0; r < 2; r++) {
        int o = lane + r * 32;
        float acc = bo2[o];
        const float* wr = Wo2 + o * 64;
        for (int f = 0; f < 64; f++) acc += wr[f] * s_v1[wid][f];
        s_v2[wid][o] = fmaxf(acc, 0.f);
    }
    __syncwarp();
    float a = s_v2[wid][lane], bve = s_v2[wid][32 + lane];
    float px = Wo3[lane] * a + Wo3[32 + lane] * bve;
    float py = Wo3[64 + lane] * a + Wo3[96 + lane] * bve;
    for (int o = 16; o > 0; o >>= 1) {
        px += __shfl_down_sync(0xffffffffu, px, o);
        py += __shfl_down_sync(0xffffffffu, py, o);
    }
    if (lane == 0) {
        float offx = px + bo3[0], offy = py + bo3[1];
        int ph = p >> 2, pw = p & 3;
        float Ax = ((float)pw + 0.5f) * 0.25f - 0.5f + offx;
        float Ay = ((float)ph + 0.5f) * 0.25f - 0.5f + offy;
        float fx = floorf(Ax), fy = floorf(Ay);
        g_geo[task] = make_float4(fx, fy, Ax - fx, Ay - fy);
    }
}

// ---------------- K3b: routing + effective per-phase matrices ----------------
__global__ void k3b_route(const float* __restrict__ Wr1, const float* __restrict__ br1,
                          const float* __restrict__ Wr2, const float* __restrict__ br2,
                          const float* __restrict__ Wq1, const float* __restrict__ bq1,
                          const float* __restrict__ Wq2, const float* __restrict__ bq2,
                          const float* __restrict__ Wq3, const float* __restrict__ bq3,
                          const float* __restrict__ wc,  const float* __restrict__ we) {
    __shared__ float s_u1[4096], s_r[64], s_q1[1024], s_q2[1024], s_rw[64];
    int tid = threadIdx.x;
    for (int i = tid; i < 4096; i += 256) {
        int o = i >> 6, fp = i & 63;
        float acc = br1[o];
        const float* wr = Wr1 + o * 64;
        for (int c = 0; c < 64; c++) acc += wr[c] * g_emb[c * 64 + fp];
        s_u1[o * 64 + fp] = fmaxf(acc, 0.f);
    }
    __syncthreads();
    if (tid < 64) {
        float acc = br2[0];
        for (int c = 0; c < 64; c++) acc += Wr2[c] * s_u1[c * 64 + tid];
        s_r[tid] = 1.f / (1.f + expf(-acc));
    }
    __syncthreads();
    for (int i = tid; i < 1024; i += 256) {
        int o = i >> 4, p = i & 15;
        float acc = bq1[o];
        for (int f = 0; f < 4; f++) acc += Wq1[o * 4 + f] * s_r[f * 16 + p];
        s_q1[o * 16 + p] = fmaxf(acc, 0.f);
    }
    __syncthreads();
    for (int i = tid; i < 1024; i += 256) {
        int o = i >> 4, p = i & 15;
        float acc = bq2[o];
        const float* wr = Wq2 + o * 64;
        for (int f = 0; f < 64; f++) acc += wr[f] * s_q1[f * 16 + p];
        s_q2[o * 16 + p] = fmaxf(acc, 0.f);
    }
    __syncthreads();
    if (tid < 64) {
        int e = tid >> 4, p = tid & 15;
        float acc = bq3[e];
        const float* wr = Wq3 + e * 64;
        for (int f = 0; f < 64; f++) acc += wr[f] * s_q2[f * 16 + p];
        s_rw[tid] = 1.f / (1.f + expf(-acc));
    }
    __syncthreads();
    for (int i = tid; i < 8192; i += 256) {
        int p = i >> 9, rem = i & 511;
        float a = 0.f, b2 = 0.f;
        for (int e = 0; e < 4; e++) {
            float rwv = s_rw[e * 16 + p];
            a  += rwv * wc[e * 512 + rem];
            b2 += rwv * we[e * 512 + rem];
        }
        g_Wc[i] = a;
        g_We[i] = b2;
    }
}

// ---------------- K4: main per-pixel kernel ----------------
__global__ void __launch_bounds__(256, 2)
k4_main(float* __restrict__ out) {
    extern __shared__ float sm[];
    float*  s_fea = sm;                          // 256*68 = 17408
    float4* s_geo = (float4*)(sm + 17408);       // 256 float4
    float*  s_Wc  = sm + 18432;                  // 4*516
    float*  s_We  = sm + 20496;                  // 4*516
    int tid = threadIdx.x;
    int b = blockIdx.x >> 8, ho = blockIdx.x & 255;
    int mh = ho >> 2, ph = ho & 3;

    { int c = tid >> 2, pwl = tid & 3; s_geo[tid] = g_geo[c * 16 + ph * 4 + pwl]; }
    for (int i = tid; i < 2048; i += 256) {
        int pwl = i >> 9, rem = i & 511;
        s_Wc[pwl * 516 + rem] = g_Wc[(ph * 4 + pwl) * 512 + rem];
        s_We[pwl * 516 + rem] = g_We[(ph * 4 + pwl) * 512 + rem];
    }
    __syncthreads();

    int pw = tid & 3, mw = tid >> 2;
    const float* xb = g_xpad + b * 64 * PLANE;
    float4 buf;
    for (int c = 0; c < 64; c++) {
        float4 geo = s_geo[c * 4 + pw];
        int x0 = mw + (int)geo.x + 2;
        int y0 = mh + (int)geo.y + 2;
        float wx = geo.z, wy = geo.w;
        int cx0 = min(max(x0, 0), 67), cx1 = min(max(x0 + 1, 0), 67);
        int cy0 = min(max(y0, 0), 67), cy1 = min(max(y0 + 1, 0), 67);
        const float* pl = xb + c * PLANE;
        float v00 = pl[cy0 * 68 + cx0], v01 = pl[cy0 * 68 + cx1];
        float v10 = pl[cy1 * 68 + cx0], v11 = pl[cy1 * 68 + cx1];
        float top = v00 + wx * (v01 - v00);
        float bot = v10 + wx * (v11 - v10);
        float v = top + wy * (bot - top);
        int q = c & 3;
        if (q == 0) buf.x = v; else if (q == 1) buf.y = v; else if (q == 2) buf.z = v;
        else { buf.w = v; *(float4*)&s_fea[tid * 68 + (c - 3)] = buf; }
    }
    __syncthreads();

    const float* Wcp = s_Wc + pw * 516;
    const float* Wep = s_We + pw * 516;
    const float* frow = s_fea + tid * 68;
    float mid[8];
#pragma unroll
    for (int kk = 0; kk < 8; kk++) mid[kk] = 0.f;
#pragma unroll 4
    for (int c4 = 0; c4 < 16; c4++) {
        float4 f4 = *(const float4*)&frow[4 * c4];
#pragma unroll
        for (int kk = 0; kk < 8; kk++) {
            float4 w4 = *(const float4*)&Wcp[kk * 64 + 4 * c4];
            mid[kk] += f4.x * w4.x + f4.y * w4.y + f4.z * w4.z + f4.w * w4.w;
        }
    }
    float* obase = out + (b * 64 * 256 + ho) * 256 + tid;
#pragma unroll 4
    for (int c4 = 0; c4 < 16; c4++) {
        float4 f4 = *(const float4*)&frow[4 * c4];
        float r0[4] = {f4.x, f4.y, f4.z, f4.w};
#pragma unroll
        for (int j = 0; j < 4; j++) {
            int c = 4 * c4 + j;
            float4 wa = *(const float4*)&Wep[c * 8];
            float4 wb = *(const float4*)&Wep[c * 8 + 4];
            float o = r0[j] + wa.x * mid[0] + wa.y * mid[1] + wa.z * mid[2] + wa.w * mid[3]
                            + wb.x * mid[4] + wb.y * mid[5] + wb.z * mid[6] + wb.w * mid[7];
            obase[c * 65536] = o;
        }
    }
}

extern "C" void kernel_launch(void* const* d_in, const int* in_sizes, int n_in,
                              void* d_out, int out_size) {
    const float* x   = (const float*)d_in[0];
    const float* wc  = (const float*)d_in[1];
    const float* we  = (const float*)d_in[2];
    const float* Wb1 = (const float*)d_in[3];
    const float* bb1 = (const float*)d_in[4];
    const float* Wb2 = (const float*)d_in[5];
    const float* bb2 = (const float*)d_in[6];
    const float* Wr1 = (const float*)d_in[7];
    const float* br1 = (const float*)d_in[8];
    const float* Wr2 = (const float*)d_in[9];
    const float* br2 = (const float*)d_in[10];
    const float* Wq1 = (const float*)d_in[11];
    const float* bq1 = (const float*)d_in[12];
    const float* Wq2 = (const float*)d_in[13];
    const float* bq2 = (const float*)d_in[14];
    const float* Wq3 = (const float*)d_in[15];
    const float* bq3 = (const float*)d_in[16];
    const float* Wo1 = (const float*)d_in[17];
    const float* bo1 = (const float*)d_in[18];
    const float* Wo2 = (const float*)d_in[19];
    const float* bo2 = (const float*)d_in[20];
    const float* Wo3 = (const float*)d_in[21];
    const float* bo3 = (const float*)d_in[22];
    float* out = (float*)d_out;

    static bool attr_done = false;
    if (!attr_done) {
        cudaFuncSetAttribute(k4_main, cudaFuncAttributeMaxDynamicSharedMemorySize, 22560 * 4);
        attr_done = true;
    }

    k1_pad<<<256, 256>>>(x);
    k2_emb<<<1, 256>>>(Wb1, bb1, Wb2, bb2);
    k3a_off<<<128, 256>>>(Wo1, bo1, Wo2, bo2, Wo3, bo3);
    k3b_route<<<1, 256>>>(Wr1, br1, Wr2, br2, Wq1, bq1, Wq2, bq2, Wq3, bq3, wc, we);
    k4_main<<<1024, 256, 22560 * 4>>>(out);
}

// round 4
// speedup vs baseline: 1.1944x; 1.1944x over previous
#include <cuda_runtime.h>
#include <math.h>

#define PADW 68
#define PLANE (PADW * PADW)   // 4624

__device__ float  g_xpad[256 * PLANE];
__device__ float  g_psum[256];
__device__ float  g_emb[4096];     // [c][f*16+p]
__device__ float  g_r[64];         // [f*16+p]
__device__ float4 g_geo[1024];     // [c*16+p] = (floor(Ax), floor(Ay), wx, wy)
__device__ float  g_Wc[8192];      // [p][k][c]
__device__ float  g_We[8192];      // [p][c][k]

// ---------------- K1: zero-pad copy + per-(b,c) plane sum ----------------
__global__ void k1_pad(const float* __restrict__ x) {
    int bc = blockIdx.x, tid = threadIdx.x;
    const float* src = x + bc * 4096;
    float* dst = g_xpad + bc * PLANE;
    float s = 0.f;
    for (int i = tid; i < PLANE; i += 256) {
        int r = i / PADW, cl = i - r * PADW;
        int rr = r - 2, cc = cl - 2;
        float v = 0.f;
        if ((unsigned)rr < 64u && (unsigned)cc < 64u) v = src[rr * 64 + cc];
        dst[i] = v;
        s += v;
    }
    __shared__ float red[8];
    for (int o = 16; o > 0; o >>= 1) s += __shfl_down_sync(0xffffffffu, s, o);
    if ((tid & 31) == 0) red[tid >> 5] = s;
    __syncthreads();
    if (tid < 8) {
        s = red[tid];
        for (int o = 4; o > 0; o >>= 1) s += __shfl_down_sync(0xffu, s, o);
        if (tid == 0) g_psum[bc] = s;
    }
}

// ---------------- K2: emb[o][fp], one block per o ----------------
__global__ void k2_emb(const float* __restrict__ Wb1, const float* __restrict__ bb1,
                       const float* __restrict__ Wb2, const float* __restrict__ bb2) {
    __shared__ float s_cm[64], s_S[128], s_t1[4096], s_w[64];
    int o = blockIdx.x, tid = threadIdx.x;   // 64 threads
    s_cm[tid] = (g_psum[tid] + g_psum[64 + tid] + g_psum[128 + tid] + g_psum[192 + tid])
                * (1.0f / 16384.0f);
    s_w[tid] = Wb2[o * 64 + tid];
    __syncthreads();
    {
        float s0 = 0.f, s1 = 0.f;
        const float* row = Wb1 + tid * 64;
#pragma unroll 8
        for (int j = 0; j < 64; j++) { float w = row[j]; s0 += w * s_cm[j]; s1 += w; }
        s_S[tid] = s0; s_S[64 + tid] = s1;
    }
    __syncthreads();
    for (int i = tid; i < 4096; i += 64) {
        int c = i >> 6, fp = i & 63, f = fp >> 4, p = fp & 15;
        float meta = (f == 0) ? 1.f : (f == 1) ? 0.25f
                   : (f == 2) ? ((float)(p >> 2) * 0.25f - 0.375f)
                              : ((float)(p & 3) * 0.25f - 0.375f);
        float base = (f == 0) ? s_S[c] : s_S[64 + c];
        s_t1[c * 64 + fp] = fmaxf(meta * base + bb1[c], 0.f);
    }
    __syncthreads();
    {
        float acc = bb2[o];
#pragma unroll 8
        for (int c = 0; c < 64; c++) acc += s_w[c] * s_t1[c * 64 + tid];
        g_emb[o * 64 + tid] = fmaxf(acc, 0.f);
    }
}

// ---------------- K3a: offset head, one warp per (c,p) task ----------------
__global__ void k3a_off(const float* __restrict__ Wo1, const float* __restrict__ bo1,
                        const float* __restrict__ Wo2, const float* __restrict__ bo2,
                        const float* __restrict__ Wo3, const float* __restrict__ bo3) {
    __shared__ float s_v1[8][64], s_v2[8][64];
    int wid = threadIdx.x >> 5, lane = threadIdx.x & 31;
    int task = blockIdx.x * 8 + wid;   // c*16+p
    int c = task >> 4, p = task & 15;
    float e0 = g_emb[c * 64 + p],      e1 = g_emb[c * 64 + 16 + p];
    float e2 = g_emb[c * 64 + 32 + p], e3 = g_emb[c * 64 + 48 + p];
    for (int r = 0; r < 2; r++) {
        int o = lane + r * 32;
        float v = bo1[o] + Wo1[o*4]*e0 + Wo1[o*4+1]*e1 + Wo1[o*4+2]*e2 + Wo1[o*4+3]*e3;
        s_v1[wid][o] = fmaxf(v, 0.f);
    }
    __syncwarp();
    for (int r = 0; r < 2; r++) {
        int o = lane + r * 32;
        float acc = bo2[o];
        const float* wr = Wo2 + o * 64;
#pragma unroll 8
        for (int f = 0; f < 64; f++) acc += wr[f] * s_v1[wid][f];
        s_v2[wid][o] = fmaxf(acc, 0.f);
    }
    __syncwarp();
    float a = s_v2[wid][lane], bve = s_v2[wid][32 + lane];
    float px = Wo3[lane] * a + Wo3[32 + lane] * bve;
    float py = Wo3[64 + lane] * a + Wo3[96 + lane] * bve;
    for (int o = 16; o > 0; o >>= 1) {
        px += __shfl_down_sync(0xffffffffu, px, o);
        py += __shfl_down_sync(0xffffffffu, py, o);
    }
    if (lane == 0) {
        float offx = px + bo3[0], offy = py + bo3[1];
        int ph = p >> 2, pw = p & 3;
        float Ax = ((float)pw + 0.5f) * 0.25f - 0.5f + offx;
        float Ay = ((float)ph + 0.5f) * 0.25f - 0.5f + offy;
        float fx = floorf(Ax), fy = floorf(Ay);
        g_geo[task] = make_float4(fx, fy, Ax - fx, Ay - fy);
    }
}

// ---------------- K3r: routing r[fp] directly, one block per fp ----------------
__global__ void k3r_route(const float* __restrict__ Wr1, const float* __restrict__ br1,
                          const float* __restrict__ Wr2, const float* __restrict__ br2) {
    __shared__ float s_w[64 * 65];   // Wr1, padded rows
    __shared__ float s_e[64];
    __shared__ float s_part[256];
    int fp = blockIdx.x, tid = threadIdx.x;
    for (int i = tid; i < 4096; i += 256) {
        int r = i >> 6, cl = i & 63;
        s_w[r * 65 + cl] = Wr1[i];
    }
    if (tid < 64) s_e[tid] = g_emb[tid * 64 + fp];
    __syncthreads();
    int c = tid >> 2, jg = tid & 3;
    float acc = 0.f;
    const float* wr = s_w + c * 65 + jg * 16;
    const float* er = s_e + jg * 16;
#pragma unroll
    for (int j = 0; j < 16; j++) acc += wr[j] * er[j];
    s_part[tid] = acc;
    __syncthreads();
    if (tid < 64) {
        float u = s_part[tid*4] + s_part[tid*4+1] + s_part[tid*4+2] + s_part[tid*4+3] + br1[tid];
        s_part[tid] = fmaxf(u, 0.f) * Wr2[tid];
    }
    __syncthreads();
    if (tid < 32) {
        float v = s_part[tid] + s_part[tid + 32];
        for (int o = 16; o > 0; o >>= 1) v += __shfl_down_sync(0xffffffffu, v, o);
        if (tid == 0) g_r[fp] = 1.f / (1.f + expf(-(v + br2[0])));
    }
}

// ---------------- K3b2: q-heads + effective per-phase matrices ----------------
__global__ void k3b2_mix(const float* __restrict__ Wq1, const float* __restrict__ bq1,
                         const float* __restrict__ Wq2, const float* __restrict__ bq2,
                         const float* __restrict__ Wq3, const float* __restrict__ bq3,
                         const float* __restrict__ wc,  const float* __restrict__ we) {
    __shared__ float s_r[64], s_q1[1024], s_q2[1024], s_rw[64], s_wq2[4096];
    int tid = threadIdx.x;
    if (tid < 64) s_r[tid] = g_r[tid];
    for (int i = tid; i < 4096; i += 256) s_wq2[i] = Wq2[i];
    __syncthreads();
    for (int i = tid; i < 1024; i += 256) {
        int o = i >> 4, p = i & 15;
        float acc = bq1[o];
#pragma unroll
        for (int f = 0; f < 4; f++) acc += Wq1[o * 4 + f] * s_r[f * 16 + p];
        s_q1[o * 16 + p] = fmaxf(acc, 0.f);
    }
    __syncthreads();
    for (int i = tid; i < 1024; i += 256) {
        int o = i >> 4, p = i & 15;
        float acc = bq2[o];
        const float* wr = s_wq2 + o * 64;
#pragma unroll 8
        for (int f = 0; f < 64; f++) acc += wr[f] * s_q1[f * 16 + p];
        s_q2[o * 16 + p] = fmaxf(acc, 0.f);
    }
    __syncthreads();
    if (tid < 64) {
        int e = tid >> 4, p = tid & 15;
        float acc = bq3[e];
        const float* wr = Wq3 + e * 64;
#pragma unroll 8
        for (int f = 0; f < 64; f++) acc += wr[f] * s_q2[f * 16 + p];
        s_rw[tid] = 1.f / (1.f + expf(-acc));
    }
    __syncthreads();
    for (int i = tid; i < 8192; i += 256) {
        int p = i >> 9, rem = i & 511;
        float a = 0.f, b2 = 0.f;
#pragma unroll
        for (int e = 0; e < 4; e++) {
            float rwv = s_rw[e * 16 + p];
            a  += rwv * wc[e * 512 + rem];
            b2 += rwv * we[e * 512 + rem];
        }
        g_Wc[i] = a;
        g_We[i] = b2;
    }
}

// ---------------- K4: main per-pixel kernel ----------------
__global__ void __launch_bounds__(256, 2)
k4_main(float* __restrict__ out) {
    extern __shared__ float sm[];
    float*  s_fea = sm;                          // 256*68 = 17408
    float4* s_geo = (float4*)(sm + 17408);       // 256 float4
    float*  s_Wc  = sm + 18432;                  // 4*516
    float*  s_We  = sm + 20496;                  // 4*516
    int tid = threadIdx.x;
    int b = blockIdx.x >> 8, ho = blockIdx.x & 255;
    int mh = ho >> 2, ph = ho & 3;

    { int c = tid >> 2, pwl = tid & 3; s_geo[tid] = g_geo[c * 16 + ph * 4 + pwl]; }
    for (int i = tid; i < 2048; i += 256) {
        int pwl = i >> 9, rem = i & 511;
        s_Wc[pwl * 516 + rem] = g_Wc[(ph * 4 + pwl) * 512 + rem];
        s_We[pwl * 516 + rem] = g_We[(ph * 4 + pwl) * 512 + rem];
    }
    __syncthreads();

    int pw = tid & 3, mw = tid >> 2;
    const float* xb = g_xpad + b * 64 * PLANE;
    float4 buf;
    for (int c = 0; c < 64; c++) {
        float4 geo = s_geo[c * 4 + pw];
        int x0 = mw + (int)geo.x + 2;
        int y0 = mh + (int)geo.y + 2;
        float wx = geo.z, wy = geo.w;
        int cx0 = min(max(x0, 0), 67), cx1 = min(max(x0 + 1, 0), 67);
        int cy0 = min(max(y0, 0), 67), cy1 = min(max(y0 + 1, 0), 67);
        const float* pl = xb + c * PLANE;
        float v00 = pl[cy0 * 68 + cx0], v01 = pl[cy0 * 68 + cx1];
        float v10 = pl[cy1 * 68 + cx0], v11 = pl[cy1 * 68 + cx1];
        float top = v00 + wx * (v01 - v00);
        float bot = v10 + wx * (v11 - v10);
        float v = top + wy * (bot - top);
        int q = c & 3;
        if (q == 0) buf.x = v; else if (q == 1) buf.y = v; else if (q == 2) buf.z = v;
        else { buf.w = v; *(float4*)&s_fea[tid * 68 + (c - 3)] = buf; }
    }
    __syncthreads();

    const float* Wcp = s_Wc + pw * 516;
    const float* Wep = s_We + pw * 516;
    const float* frow = s_fea + tid * 68;
    float mid[8];
#pragma unroll
    for (int kk = 0; kk < 8; kk++) mid[kk] = 0.f;
#pragma unroll 4
    for (int c4 = 0; c4 < 16; c4++) {
        float4 f4 = *(const float4*)&frow[4 * c4];
#pragma unroll
        for (int kk = 0; kk < 8; kk++) {
            float4 w4 = *(const float4*)&Wcp[kk * 64 + 4 * c4];
            mid[kk] += f4.x * w4.x + f4.y * w4.y + f4.z * w4.z + f4.w * w4.w;
        }
    }
    float* obase = out + (b * 64 * 256 + ho) * 256 + tid;
#pragma unroll 4
    for (int c4 = 0; c4 < 16; c4++) {
        float4 f4 = *(const float4*)&frow[4 * c4];
        float r0[4] = {f4.x, f4.y, f4.z, f4.w};
#pragma unroll
        for (int j = 0; j < 4; j++) {
            int c = 4 * c4 + j;
            float4 wa = *(const float4*)&Wep[c * 8];
            float4 wb = *(const float4*)&Wep[c * 8 + 4];
            float o = r0[j] + wa.x * mid[0] + wa.y * mid[1] + wa.z * mid[2] + wa.w * mid[3]
                            + wb.x * mid[4] + wb.y * mid[5] + wb.z * mid[6] + wb.w * mid[7];
            obase[c * 65536] = o;
        }
    }
}

extern "C" void kernel_launch(void* const* d_in, const int* in_sizes, int n_in,
                              void* d_out, int out_size) {
    const float* x   = (const float*)d_in[0];
    const float* wc  = (const float*)d_in[1];
    const float* we  = (const float*)d_in[2];
    const float* Wb1 = (const float*)d_in[3];
    const float* bb1 = (const float*)d_in[4];
    const float* Wb2 = (const float*)d_in[5];
    const float* bb2 = (const float*)d_in[6];
    const float* Wr1 = (const float*)d_in[7];
    const float* br1 = (const float*)d_in[8];
    const float* Wr2 = (const float*)d_in[9];
    const float* br2 = (const float*)d_in[10];
    const float* Wq1 = (const float*)d_in[11];
    const float* bq1 = (const float*)d_in[12];
    const float* Wq2 = (const float*)d_in[13];
    const float* bq2 = (const float*)d_in[14];
    const float* Wq3 = (const float*)d_in[15];
    const float* bq3 = (const float*)d_in[16];
    const float* Wo1 = (const float*)d_in[17];
    const float* bo1 = (const float*)d_in[18];
    const float* Wo2 = (const float*)d_in[19];
    const float* bo2 = (const float*)d_in[20];
    const float* Wo3 = (const float*)d_in[21];
    const float* bo3 = (const float*)d_in[22];
    float* out = (float*)d_out;

    cudaFuncSetAttribute(k4_main, cudaFuncAttributeMaxDynamicSharedMemorySize, 22560 * 4);

    k1_pad<<<256, 256>>>(x);
    k2_emb<<<64, 64>>>(Wb1, bb1, Wb2, bb2);
    k3a_off<<<128, 256>>>(Wo1, bo1, Wo2, bo2, Wo3, bo3);
    k3r_route<<<64, 256>>>(Wr1, br1, Wr2, br2);
    k3b2_mix<<<1, 256>>>(Wq1, bq1, Wq2, bq2, Wq3, bq3, wc, we);
    k4_main<<<1024, 256, 22560 * 4>>>(out);
}

// round 5
// speedup vs baseline: 1.4431x; 1.2082x over previous
#include <cuda_runtime.h>
#include <math.h>

__device__ float  g_cmean[64];
__device__ float  g_emb[4096];     // [c][f*16+p]
__device__ float  g_r[64];         // [f*16+p]
__device__ float4 g_geo[1024];     // [c*16+p] = (floor(Ax), floor(Ay), wx, wy)
__device__ float  g_Wc[8192];      // [p][k][c]
__device__ float  g_We[8192];      // [p][c][k]

// ---------------- kM: channel means, one block per c ----------------
__global__ void kM_mean(const float* __restrict__ x) {
    int c = blockIdx.x, tid = threadIdx.x;
    float s = 0.f;
    for (int b = 0; b < 4; b++) {
        const float4* p = (const float4*)(x + b * 262144 + c * 4096);
        for (int i = tid; i < 1024; i += 256) {
            float4 v = p[i];
            s += v.x + v.y + v.z + v.w;
        }
    }
    __shared__ float red[8];
    for (int o = 16; o > 0; o >>= 1) s += __shfl_down_sync(0xffffffffu, s, o);
    if ((tid & 31) == 0) red[tid >> 5] = s;
    __syncthreads();
    if (tid < 8) {
        s = red[tid];
        for (int o = 4; o > 0; o >>= 1) s += __shfl_down_sync(0xffu, s, o);
        if (tid == 0) g_cmean[c] = s * (1.0f / 16384.0f);
    }
}

// ---------------- K2: emb[o][fp], one block per o, t1 on the fly ----------------
__global__ void k2_emb(const float* __restrict__ Wb1, const float* __restrict__ bb1,
                       const float* __restrict__ Wb2, const float* __restrict__ bb2) {
    __shared__ float s_S0[64], s_S1[64], s_w[64], s_b1[64];
    int o = blockIdx.x, tid = threadIdx.x;   // 64 threads, tid = fp
    __shared__ float s_cm[64];
    s_cm[tid] = g_cmean[tid];
    s_w[tid]  = Wb2[o * 64 + tid];
    s_b1[tid] = bb1[tid];
    __syncthreads();
    {
        float s0 = 0.f, s1 = 0.f;
        const float* row = Wb1 + tid * 64;
#pragma unroll 8
        for (int j = 0; j < 64; j++) { float w = row[j]; s0 += w * s_cm[j]; s1 += w; }
        s_S0[tid] = s0; s_S1[tid] = s1;
    }
    __syncthreads();
    {
        int f = tid >> 4, p = tid & 15;
        float meta = (f == 0) ? 1.f : (f == 1) ? 0.25f
                   : (f == 2) ? ((float)(p >> 2) * 0.25f - 0.375f)
                              : ((float)(p & 3) * 0.25f - 0.375f);
        const float* S = (f == 0) ? s_S0 : s_S1;
        float acc = bb2[o];
#pragma unroll 8
        for (int c = 0; c < 64; c++)
            acc += s_w[c] * fmaxf(meta * S[c] + s_b1[c], 0.f);
        g_emb[o * 64 + tid] = fmaxf(acc, 0.f);
    }
}

// ---------------- K3m: blocks 0..127 offset head; 128..191 routing r ----------------
__global__ void k3m(const float* __restrict__ Wo1, const float* __restrict__ bo1,
                    const float* __restrict__ Wo2, const float* __restrict__ bo2,
                    const float* __restrict__ Wo3, const float* __restrict__ bo3,
                    const float* __restrict__ Wr1, const float* __restrict__ br1,
                    const float* __restrict__ Wr2, const float* __restrict__ br2) {
    __shared__ float sh[5120];
    int tid = threadIdx.x;
    if (blockIdx.x < 128) {
        // ---- offset head: 8 warps, one (c,p) task per warp ----
        float* s_wo2 = sh;                 // 4096
        float* s_v1  = sh + 4096;          // 8*64
        float* s_v2  = sh + 4608;          // 8*64
        for (int i = tid; i < 4096; i += 256) s_wo2[i] = Wo2[i];
        __syncthreads();
        int wid = tid >> 5, lane = tid & 31;
        int task = blockIdx.x * 8 + wid;   // c*16+p
        int c = task >> 4, p = task & 15;
        float e0 = g_emb[c * 64 + p],      e1 = g_emb[c * 64 + 16 + p];
        float e2 = g_emb[c * 64 + 32 + p], e3 = g_emb[c * 64 + 48 + p];
        for (int r = 0; r < 2; r++) {
            int o = lane + r * 32;
            float v = bo1[o] + Wo1[o*4]*e0 + Wo1[o*4+1]*e1 + Wo1[o*4+2]*e2 + Wo1[o*4+3]*e3;
            s_v1[wid * 64 + o] = fmaxf(v, 0.f);
        }
        __syncwarp();
        for (int r = 0; r < 2; r++) {
            int o = lane + r * 32;
            float acc = bo2[o];
            const float* wr = s_wo2 + o * 64;
            const float* v1 = s_v1 + wid * 64;
#pragma unroll 8
            for (int f = 0; f < 64; f++) acc += wr[f] * v1[f];
            s_v2[wid * 64 + o] = fmaxf(acc, 0.f);
        }
        __syncwarp();
        float a = s_v2[wid * 64 + lane], bve = s_v2[wid * 64 + 32 + lane];
        float px = Wo3[lane] * a + Wo3[32 + lane] * bve;
        float py = Wo3[64 + lane] * a + Wo3[96 + lane] * bve;
        for (int o = 16; o > 0; o >>= 1) {
            px += __shfl_down_sync(0xffffffffu, px, o);
            py += __shfl_down_sync(0xffffffffu, py, o);
        }
        if (lane == 0) {
            float offx = px + bo3[0], offy = py + bo3[1];
            int ph = p >> 2, pw = p & 3;
            float Ax = ((float)pw + 0.5f) * 0.25f - 0.5f + offx;
            float Ay = ((float)ph + 0.5f) * 0.25f - 0.5f + offy;
            float fx = floorf(Ax), fy = floorf(Ay);
            g_geo[task] = make_float4(fx, fy, Ax - fx, Ay - fy);
        }
    } else {
        // ---- routing r[fp], one block per fp ----
        float* s_w    = sh;                // 64*65
        float* s_e    = sh + 4160;         // 64
        float* s_part = sh + 4224;         // 256
        int fp = blockIdx.x - 128;
        for (int i = tid; i < 4096; i += 256) {
            int r = i >> 6, cl = i & 63;
            s_w[r * 65 + cl] = Wr1[i];
        }
        if (tid < 64) s_e[tid] = g_emb[tid * 64 + fp];
        __syncthreads();
        int c = tid >> 2, jg = tid & 3;
        float acc = 0.f;
        const float* wr = s_w + c * 65 + jg * 16;
        const float* er = s_e + jg * 16;
#pragma unroll
        for (int j = 0; j < 16; j++) acc += wr[j] * er[j];
        s_part[tid] = acc;
        __syncthreads();
        if (tid < 64) {
            float u = s_part[tid*4] + s_part[tid*4+1] + s_part[tid*4+2] + s_part[tid*4+3] + br1[tid];
            s_part[tid] = fmaxf(u, 0.f) * Wr2[tid];
        }
        __syncthreads();
        if (tid < 32) {
            float v = s_part[tid] + s_part[tid + 32];
            for (int o = 16; o > 0; o >>= 1) v += __shfl_down_sync(0xffffffffu, v, o);
            if (tid == 0) g_r[fp] = 1.f / (1.f + expf(-(v + br2[0])));
        }
    }
}

// ---------------- K3b2: q-heads + effective matrices, one block per phase p ----------------
__global__ void k3b2_mix(const float* __restrict__ Wq1, const float* __restrict__ bq1,
                         const float* __restrict__ Wq2, const float* __restrict__ bq2,
                         const float* __restrict__ Wq3, const float* __restrict__ bq3,
                         const float* __restrict__ wc,  const float* __restrict__ we) {
    __shared__ float s_q1[64], s_q2[64], s_rw[4], s_wq2[4096], s_r[4];
    int p = blockIdx.x, tid = threadIdx.x;
    if (tid < 4) s_r[tid] = g_r[tid * 16 + p];
    for (int i = tid; i < 4096; i += 256) s_wq2[i] = Wq2[i];
    __syncthreads();
    if (tid < 64) {
        float acc = bq1[tid];
#pragma unroll
        for (int f = 0; f < 4; f++) acc += Wq1[tid * 4 + f] * s_r[f];
        s_q1[tid] = fmaxf(acc, 0.f);
    }
    __syncthreads();
    if (tid < 64) {
        float acc = bq2[tid];
        const float* wr = s_wq2 + tid * 64;
#pragma unroll 8
        for (int f = 0; f < 64; f++) acc += wr[f] * s_q1[f];
        s_q2[tid] = fmaxf(acc, 0.f);
    }
    __syncthreads();
    if (tid < 4) {
        float acc = bq3[tid];
        const float* wr = Wq3 + tid * 64;
#pragma unroll 8
        for (int f = 0; f < 64; f++) acc += wr[f] * s_q2[f];
        s_rw[tid] = 1.f / (1.f + expf(-acc));
    }
    __syncthreads();
    float rw0 = s_rw[0], rw1 = s_rw[1], rw2 = s_rw[2], rw3 = s_rw[3];
    for (int rem = tid; rem < 512; rem += 256) {
        float a = rw0 * wc[rem]       + rw1 * wc[512 + rem]
                + rw2 * wc[1024 + rem] + rw3 * wc[1536 + rem];
        float b2 = rw0 * we[rem]       + rw1 * we[512 + rem]
                 + rw2 * we[1024 + rem] + rw3 * we[1536 + rem];
        g_Wc[p * 512 + rem] = a;
        g_We[p * 512 + rem] = b2;
    }
}

// ---------------- K4: main per-pixel kernel ----------------
__global__ void __launch_bounds__(256, 2)
k4_main(const float* __restrict__ x, float* __restrict__ out) {
    extern __shared__ float sm[];
    float*  s_fea = sm;                          // 256*68 = 17408
    float4* s_geo = (float4*)(sm + 17408);       // 256 float4
    float*  s_Wc  = sm + 18432;                  // 4*516
    float*  s_We  = sm + 20496;                  // 4*516
    int tid = threadIdx.x;
    int b = blockIdx.x >> 8, ho = blockIdx.x & 255;
    int mh = ho >> 2, ph = ho & 3;

    { int c = tid >> 2, pwl = tid & 3; s_geo[tid] = g_geo[c * 16 + ph * 4 + pwl]; }
    for (int i = tid; i < 2048; i += 256) {
        int pwl = i >> 9, rem = i & 511;
        s_Wc[pwl * 516 + rem] = g_Wc[(ph * 4 + pwl) * 512 + rem];
        s_We[pwl * 516 + rem] = g_We[(ph * 4 + pwl) * 512 + rem];
    }
    __syncthreads();

    // ---- gather: pw warp-uniform; storage row = tid; pixel w = 4*mw + pw ----
    int pwg = tid >> 6, mw = tid & 63;
    const float* xb = x + b * 262144;
    float4 buf;
    for (int c = 0; c < 64; c++) {
        float4 geo = s_geo[c * 4 + pwg];          // warp-uniform broadcast
        int x0 = mw + (int)geo.x;
        int y0 = mh + (int)geo.y;
        float wx = geo.z, wy = geo.w;
        int cx0 = min(max(x0, 0), 63),     cx1 = min(max(x0 + 1, 0), 63);
        int cy0 = min(max(y0, 0), 63),     cy1 = min(max(y0 + 1, 0), 63);
        float mx0 = ((unsigned)x0       < 64u) ? 1.f : 0.f;
        float mx1 = ((unsigned)(x0 + 1) < 64u) ? 1.f : 0.f;
        float my0 = ((unsigned)y0       < 64u) ? 1.f : 0.f;
        float my1 = ((unsigned)(y0 + 1) < 64u) ? 1.f : 0.f;
        const float* pl = xb + c * 4096;
        float v00 = pl[cy0 * 64 + cx0] * (my0 * mx0);
        float v01 = pl[cy0 * 64 + cx1] * (my0 * mx1);
        float v10 = pl[cy1 * 64 + cx0] * (my1 * mx0);
        float v11 = pl[cy1 * 64 + cx1] * (my1 * mx1);
        float top = v00 + wx * (v01 - v00);
        float bot = v10 + wx * (v11 - v10);
        float v = top + wy * (bot - top);
        int q = c & 3;
        if (q == 0) buf.x = v; else if (q == 1) buf.y = v; else if (q == 2) buf.z = v;
        else { buf.w = v; *(float4*)&s_fea[tid * 68 + (c - 3)] = buf; }
    }
    __syncthreads();

    // ---- mix/expand: row = tid, pw = tid>>6 (warp-uniform weights) ----
    const float* Wcp = s_Wc + pwg * 516;
    const float* Wep = s_We + pwg * 516;
    const float* frow = s_fea + tid * 68;
    float mid[8];
#pragma unroll
    for (int kk = 0; kk < 8; kk++) mid[kk] = 0.f;
#pragma unroll 4
    for (int c4 = 0; c4 < 16; c4++) {
        float4 f4 = *(const float4*)&frow[4 * c4];
#pragma unroll
        for (int kk = 0; kk < 8; kk++) {
            float4 w4 = *(const float4*)&Wcp[kk * 64 + 4 * c4];
            mid[kk] += f4.x * w4.x + f4.y * w4.y + f4.z * w4.z + f4.w * w4.w;
        }
    }
    int w = 4 * mw + pwg;
    float* obase = out + (b * 64 * 256 + ho) * 256 + w;
#pragma unroll 4
    for (int c4 = 0; c4 < 16; c4++) {
        float4 f4 = *(const float4*)&frow[4 * c4];
        float r0[4] = {f4.x, f4.y, f4.z, f4.w};
#pragma unroll
        for (int j = 0; j < 4; j++) {
            int c = 4 * c4 + j;
            float4 wa = *(const float4*)&Wep[c * 8];
            float4 wb = *(const float4*)&Wep[c * 8 + 4];
            float o = r0[j] + wa.x * mid[0] + wa.y * mid[1] + wa.z * mid[2] + wa.w * mid[3]
                            + wb.x * mid[4] + wb.y * mid[5] + wb.z * mid[6] + wb.w * mid[7];
            obase[c * 65536] = o;
        }
    }
}

extern "C" void kernel_launch(void* const* d_in, const int* in_sizes, int n_in,
                              void* d_out, int out_size) {
    const float* x   = (const float*)d_in[0];
    const float* wc  = (const float*)d_in[1];
    const float* we  = (const float*)d_in[2];
    const float* Wb1 = (const float*)d_in[3];
    const float* bb1 = (const float*)d_in[4];
    const float* Wb2 = (const float*)d_in[5];
    const float* bb2 = (const float*)d_in[6];
    const float* Wr1 = (const float*)d_in[7];
    const float* br1 = (const float*)d_in[8];
    const float* Wr2 = (const float*)d_in[9];
    const float* br2 = (const float*)d_in[10];
    const float* Wq1 = (const float*)d_in[11];
    const float* bq1 = (const float*)d_in[12];
    const float* Wq2 = (const float*)d_in[13];
    const float* bq2 = (const float*)d_in[14];
    const float* Wq3 = (const float*)d_in[15];
    const float* bq3 = (const float*)d_in[16];
    const float* Wo1 = (const float*)d_in[17];
    const float* bo1 = (const float*)d_in[18];
    const float* Wo2 = (const float*)d_in[19];
    const float* bo2 = (const float*)d_in[20];
    const float* Wo3 = (const float*)d_in[21];
    const float* bo3 = (const float*)d_in[22];
    float* out = (float*)d_out;

    cudaFuncSetAttribute(k4_main, cudaFuncAttributeMaxDynamicSharedMemorySize, 22560 * 4);

    kM_mean<<<64, 256>>>(x);
    k2_emb<<<64, 64>>>(Wb1, bb1, Wb2, bb2);
    k3m<<<192, 256>>>(Wo1, bo1, Wo2, bo2, Wo3, bo3, Wr1, br1, Wr2, br2);
    k3b2_mix<<<16, 256>>>(Wq1, bq1, Wq2, bq2, Wq3, bq3, wc, we);
    k4_main<<<1024, 256, 22560 * 4>>>(x, out);
}

// round 9
// speedup vs baseline: 1.7063x; 1.1824x over previous
#include <cuda_runtime.h>
#include <math.h>

__device__ float  g_cmean[64];
__device__ float4 g_geo[1024];     // [c*16+p] = (floor(Ax), floor(Ay), wx, wy)
__device__ float  g_Wc[8192];      // [p][k][c]
__device__ float  g_We[8192];      // [p][c][k]

// ---------------- kM: channel means, one block per c ----------------
__global__ void kM_mean(const float* __restrict__ x) {
    int c = blockIdx.x, tid = threadIdx.x;
    float s = 0.f;
    for (int b = 0; b < 4; b++) {
        const float4* p = (const float4*)(x + b * 262144 + c * 4096);
        for (int i = tid; i < 1024; i += 256) {
            float4 v = p[i];
            s += v.x + v.y + v.z + v.w;
        }
    }
    __shared__ float red[8];
    for (int o = 16; o > 0; o >>= 1) s += __shfl_down_sync(0xffffffffu, s, o);
    if ((tid & 31) == 0) red[tid >> 5] = s;
    __syncthreads();
    if (tid < 8) {
        s = red[tid];
        for (int o = 4; o > 0; o >>= 1) s += __shfl_down_sync(0xffu, s, o);
        if (tid == 0) g_cmean[c] = s * (1.0f / 16384.0f);
    }
}

__device__ __forceinline__ float meta_val(int f, int p) {
    return (f == 0) ? 1.f : (f == 1) ? 0.25f
         : (f == 2) ? ((float)(p >> 2) * 0.25f - 0.375f)
                    : ((float)(p & 3) * 0.25f - 0.375f);
}

// ---------------- P2: fused meta network ----------------
// blocks 0..127: offset head (8 warps, one (c,p) task per warp)
// blocks 128..143: routing + rw + effective matrices, one block per phase p
__global__ void p2_meta(const float* __restrict__ Wb1, const float* __restrict__ bb1,
                        const float* __restrict__ Wb2, const float* __restrict__ bb2,
                        const float* __restrict__ Wo1, const float* __restrict__ bo1,
                        const float* __restrict__ Wo2, const float* __restrict__ bo2,
                        const float* __restrict__ Wo3, const float* __restrict__ bo3,
                        const float* __restrict__ Wr1, const float* __restrict__ br1,
                        const float* __restrict__ Wr2, const float* __restrict__ br2,
                        const float* __restrict__ Wq1, const float* __restrict__ bq1,
                        const float* __restrict__ Wq2, const float* __restrict__ bq2,
                        const float* __restrict__ Wq3, const float* __restrict__ bq3,
                        const float* __restrict__ wc,  const float* __restrict__ we) {
    __shared__ float sh[9600];
    __shared__ float s_cm[64], s_S0[64], s_S1[64], s_b1[64];
    int tid = threadIdx.x;
    if (tid < 64) { s_cm[tid] = g_cmean[tid]; s_b1[tid] = bb1[tid]; }
    __syncthreads();
    if (tid < 64) {
        float s0 = 0.f, s1 = 0.f;
        const float* row = Wb1 + tid * 64;
#pragma unroll 8
        for (int j = 0; j < 64; j++) { float w = row[j]; s0 += w * s_cm[j]; s1 += w; }
        s_S0[tid] = s0; s_S1[tid] = s1;
    }

    if (blockIdx.x < 128) {
        // ======== offset head ========
        float* s_wo2T = sh;            // 65*64 = 4160 transposed
        float* s_v1   = sh + 4160;     // 8*64
        for (int i = tid; i < 4096; i += 256)
            s_wo2T[(i & 63) * 65 + (i >> 6)] = Wo2[i];
        __syncthreads();
        int wid = tid >> 5, lane = tid & 31;
        int task = blockIdx.x * 8 + wid;   // c*16+p
        int c = task >> 4, p = task & 15;
        // inline emb[c][f*16+p], f = 0..3
        float e[4];
        float wba = Wb2[c * 64 + lane], wbb = Wb2[c * 64 + 32 + lane];
        float b2c = bb2[c];
#pragma unroll
        for (int f = 0; f < 4; f++) {
            float mv = meta_val(f, p);
            const float* S = (f == 0) ? s_S0 : s_S1;
            float a = fmaxf(mv * S[lane] + s_b1[lane], 0.f) * wba
                    + fmaxf(mv * S[32 + lane] + s_b1[32 + lane], 0.f) * wbb;
            for (int o = 16; o > 0; o >>= 1) a += __shfl_xor_sync(0xffffffffu, a, o);
            e[f] = fmaxf(a + b2c, 0.f);
        }
#pragma unroll
        for (int r = 0; r < 2; r++) {
            int o = lane + r * 32;
            float4 w4 = *(const float4*)&Wo1[o * 4];
            float v = bo1[o] + w4.x * e[0] + w4.y * e[1] + w4.z * e[2] + w4.w * e[3];
            s_v1[wid * 64 + o] = fmaxf(v, 0.f);
        }
        __syncwarp();
        float v2[2];
#pragma unroll
        for (int r = 0; r < 2; r++) {
            int o = lane + r * 32;
            float acc = bo2[o];
            const float* v1 = s_v1 + wid * 64;
#pragma unroll 8
            for (int f = 0; f < 64; f++) acc += s_wo2T[f * 65 + o] * v1[f];
            v2[r] = fmaxf(acc, 0.f);
        }
        float px = Wo3[lane] * v2[0] + Wo3[32 + lane] * v2[1];
        float py = Wo3[64 + lane] * v2[0] + Wo3[96 + lane] * v2[1];
        for (int o = 16; o > 0; o >>= 1) {
            px += __shfl_down_sync(0xffffffffu, px, o);
            py += __shfl_down_sync(0xffffffffu, py, o);
        }
        if (lane == 0) {
            float offx = px + bo3[0], offy = py + bo3[1];
            int ph = p >> 2, pw = p & 3;
            float Ax = ((float)pw + 0.5f) * 0.25f - 0.5f + offx;
            float Ay = ((float)ph + 0.5f) * 0.25f - 0.5f + offy;
            float fx = floorf(Ax), fy = floorf(Ay);
            g_geo[task] = make_float4(fx, fy, Ax - fx, Ay - fy);
        }
    } else {
        // ======== routing + rw + effective matrices for phase p ========
        int p = blockIdx.x - 128;
        float* s_A    = sh;            // 4160: Wb2T, later Wq2T
        float* s_B    = sh + 4160;     // 4160: Wr1T
        float* s_t1   = sh + 8320;     // 256  [f*64+cc]
        float* s_emb  = sh + 8576;     // 256  [f*64+o]
        float* s_red  = sh + 8832;     // 256
        float* s_r    = sh + 9088;     // 4
        float* s_q1   = sh + 9096;     // 64
        float* s_q2   = sh + 9160;     // 64
        float* s_rw   = sh + 9224;     // 4
        for (int i = tid; i < 4096; i += 256) {
            s_A[(i & 63) * 65 + (i >> 6)] = Wb2[i];
            s_B[(i & 63) * 65 + (i >> 6)] = Wr1[i];
        }
        __syncthreads();
        {   // t1[f][cc]
            int f = tid >> 6, cc = tid & 63;
            float mv = meta_val(f, p);
            float S = (f == 0) ? s_S0[cc] : s_S1[cc];
            s_t1[f * 64 + cc] = fmaxf(mv * S + s_b1[cc], 0.f);
        }
        __syncthreads();
        {   // emb[f][o]
            int f = tid >> 6, o = tid & 63;
            float acc = bb2[o];
            const float* t1 = s_t1 + f * 64;
#pragma unroll 8
            for (int cc = 0; cc < 64; cc++) acc += s_A[cc * 65 + o] * t1[cc];
            s_emb[f * 64 + o] = fmaxf(acc, 0.f);
        }
        __syncthreads();
        // stage Wq2T over s_A (emb pass done) while computing u1 from s_B
        for (int i = tid; i < 4096; i += 256)
            s_A[(i & 63) * 65 + (i >> 6)] = Wq2[i];
        {   // u1[f][o]·Wr2[o]
            int f = tid >> 6, o = tid & 63;
            float acc = br1[o];
            const float* em = s_emb + f * 64;
#pragma unroll 8
            for (int c = 0; c < 64; c++) acc += s_B[c * 65 + o] * em[c];
            s_red[tid] = fmaxf(acc, 0.f) * Wr2[o];
        }
        __syncthreads();
        if (tid < 4) {
            float v = br2[0];
            for (int o = 0; o < 64; o++) v += s_red[tid * 64 + o];
            s_r[tid] = 1.f / (1.f + expf(-v));
        }
        __syncthreads();
        if (tid < 64) {
            float4 w4 = *(const float4*)&Wq1[tid * 4];
            float acc = bq1[tid] + w4.x * s_r[0] + w4.y * s_r[1] + w4.z * s_r[2] + w4.w * s_r[3];
            s_q1[tid] = fmaxf(acc, 0.f);
        }
        __syncthreads();
        if (tid < 64) {
            float acc = bq2[tid];
#pragma unroll 8
            for (int f = 0; f < 64; f++) acc += s_A[f * 65 + tid] * s_q1[f];
            s_q2[tid] = fmaxf(acc, 0.f);
        }
        __syncthreads();
        if (tid < 4) {
            float acc = bq3[tid];
            const float* wr = Wq3 + tid * 64;
#pragma unroll 8
            for (int f = 0; f < 64; f++) acc += wr[f] * s_q2[f];
            s_rw[tid] = 1.f / (1.f + expf(-acc));
        }
        __syncthreads();
        float rw0 = s_rw[0], rw1 = s_rw[1], rw2 = s_rw[2], rw3 = s_rw[3];
        for (int rem = tid; rem < 512; rem += 256) {
            float a = rw0 * wc[rem]        + rw1 * wc[512 + rem]
                    + rw2 * wc[1024 + rem] + rw3 * wc[1536 + rem];
            float b2 = rw0 * we[rem]        + rw1 * we[512 + rem]
                     + rw2 * we[1024 + rem] + rw3 * we[1536 + rem];
            g_Wc[p * 512 + rem] = a;
            g_We[p * 512 + rem] = b2;
        }
    }
}

// ---------------- K4: main per-pixel kernel ----------------
__global__ void __launch_bounds__(256, 2)
k4_main(const float* __restrict__ x, float* __restrict__ out) {
    extern __shared__ float sm[];
    float*  s_fea = sm;                          // 17408
    float4* s_geo = (float4*)(sm + 17408);       // 1024 floats
    float*  s_Wc  = sm + 18432;                  // 2064
    float*  s_We  = sm + 20496;                  // 2064
    float*  s_out = sm + 22560;                  // 16*280 = 4480
    int tid = threadIdx.x;
    int b = blockIdx.x >> 8, ho = blockIdx.x & 255;
    int mh = ho >> 2, ph = ho & 3;

    { int c = tid >> 2, pwl = tid & 3; s_geo[tid] = g_geo[c * 16 + ph * 4 + pwl]; }
    for (int i = tid; i < 2048; i += 256) {
        int pwl = i >> 9, rem = i & 511;
        s_Wc[pwl * 516 + rem] = g_Wc[(ph * 4 + pwl) * 512 + rem];
        s_We[pwl * 516 + rem] = g_We[(ph * 4 + pwl) * 512 + rem];
    }
    __syncthreads();

    // ---- gather: pw warp-uniform; storage row = tid; pixel w = 4*mw + pw ----
    int pwg = tid >> 6, mw = tid & 63;
    const float* xb = x + b * 262144;
    float4 buf;
    for (int c = 0; c < 64; c++) {
        float4 geo = s_geo[c * 4 + pwg];
        int x0 = mw + (int)geo.x;
        int y0 = mh + (int)geo.y;
        float wx = geo.z, wy = geo.w;
        int cx0 = min(max(x0, 0), 63),     cx1 = min(max(x0 + 1, 0), 63);
        int cy0 = min(max(y0, 0), 63),     cy1 = min(max(y0 + 1, 0), 63);
        float mx0 = ((unsigned)x0       < 64u) ? 1.f : 0.f;
        float mx1 = ((unsigned)(x0 + 1) < 64u) ? 1.f : 0.f;
        float my0 = ((unsigned)y0       < 64u) ? 1.f : 0.f;
        float my1 = ((unsigned)(y0 + 1) < 64u) ? 1.f : 0.f;
        const float* pl = xb + c * 4096;
        float v00 = pl[cy0 * 64 + cx0] * (my0 * mx0);
        float v01 = pl[cy0 * 64 + cx1] * (my0 * mx1);
        float v10 = pl[cy1 * 64 + cx0] * (my1 * mx0);
        float v11 = pl[cy1 * 64 + cx1] * (my1 * mx1);
        float top = v00 + wx * (v01 - v00);
        float bot = v10 + wx * (v11 - v10);
        float v = top + wy * (bot - top);
        int q = c & 3;
        if (q == 0) buf.x = v; else if (q == 1) buf.y = v; else if (q == 2) buf.z = v;
        else { buf.w = v; *(float4*)&s_fea[tid * 68 + (c - 3)] = buf; }
    }
    __syncthreads();

    // ---- mix/expand ----
    const float* Wcp = s_Wc + pwg * 516;
    const float* Wep = s_We + pwg * 516;
    const float* frow = s_fea + tid * 68;
    float mid[8];
#pragma unroll
    for (int kk = 0; kk < 8; kk++) mid[kk] = 0.f;
#pragma unroll 4
    for (int c4 = 0; c4 < 16; c4++) {
        float4 f4 = *(const float4*)&frow[4 * c4];
#pragma unroll
        for (int kk = 0; kk < 8; kk++) {
            float4 w4 = *(const float4*)&Wcp[kk * 64 + 4 * c4];
            mid[kk] += f4.x * w4.x + f4.y * w4.y + f4.z * w4.z + f4.w * w4.w;
        }
    }
    // ---- chunked output: smem transpose -> coalesced STG ----
    int gw = tid + 8 * (tid >> 6);                 // write skew
    int rr = (tid & 3) * 64 + (tid >> 2);          // storage row for pixel w=tid
    int gr = rr + 8 * (rr >> 6);                   // read skew
    float* ob0 = out + (b * 64 * 256 + ho) * 256 + tid;
#pragma unroll
    for (int chk = 0; chk < 4; chk++) {
        float ovals[16];
#pragma unroll
        for (int j4 = 0; j4 < 4; j4++) {
            int c4 = chk * 4 + j4;
            float4 f4 = *(const float4*)&frow[4 * c4];
            float r0[4] = {f4.x, f4.y, f4.z, f4.w};
#pragma unroll
            for (int j = 0; j < 4; j++) {
                int c = 4 * c4 + j;
                float4 wa = *(const float4*)&Wep[c * 8];
                float4 wb = *(const float4*)&Wep[c * 8 + 4];
                ovals[j4 * 4 + j] = r0[j]
                    + wa.x * mid[0] + wa.y * mid[1] + wa.z * mid[2] + wa.w * mid[3]
                    + wb.x * mid[4] + wb.y * mid[5] + wb.z * mid[6] + wb.w * mid[7];
            }
        }
        __syncthreads();   // previous chunk's reads complete
#pragma unroll
        for (int cc = 0; cc < 16; cc++) s_out[cc * 280 + gw] = ovals[cc];
        __syncthreads();
        float* ob = ob0 + chk * 16 * 65536;
#pragma unroll
        for (int cc = 0; cc < 16; cc++) ob[cc * 65536] = s_out[cc * 280 + gr];
    }
}

extern "C" void kernel_launch(void* const* d_in, const int* in_sizes, int n_in,
                              void* d_out, int out_size) {
    const float* x   = (const float*)d_in[0];
    const float* wc  = (const float*)d_in[1];
    const float* we  = (const float*)d_in[2];
    const float* Wb1 = (const float*)d_in[3];
    const float* bb1 = (const float*)d_in[4];
    const float* Wb2 = (const float*)d_in[5];
    const float* bb2 = (const float*)d_in[6];
    const float* Wr1 = (const float*)d_in[7];
    const float* br1 = (const float*)d_in[8];
    const float* Wr2 = (const float*)d_in[9];
    const float* br2 = (const float*)d_in[10];
    const float* Wq1 = (const float*)d_in[11];
    const float* bq1 = (const float*)d_in[12];
    const float* Wq2 = (const float*)d_in[13];
    const float* bq2 = (const float*)d_in[14];
    const float* Wq3 = (const float*)d_in[15];
    const float* bq3 = (const float*)d_in[16];
    const float* Wo1 = (const float*)d_in[17];
    const float* bo1 = (const float*)d_in[18];
    const float* Wo2 = (const float*)d_in[19];
    const float* bo2 = (const float*)d_in[20];
    const float* Wo3 = (const float*)d_in[21];
    const float* bo3 = (const float*)d_in[22];
    float* out = (float*)d_out;

    cudaFuncSetAttribute(k4_main, cudaFuncAttributeMaxDynamicSharedMemorySize, 27040 * 4);

    kM_mean<<<64, 256>>>(x);
    p2_meta<<<144, 256>>>(Wb1, bb1, Wb2, bb2, Wo1, bo1, Wo2, bo2, Wo3, bo3,
                          Wr1, br1, Wr2, br2, Wq1, bq1, Wq2, bq2, Wq3, bq3, wc, we);
    k4_main<<<1024, 256, 27040 * 4>>>(x, out);
}

// round 11
// speedup vs baseline: 2.1493x; 1.2597x over previous
#include <cuda_runtime.h>
#include <math.h>

__device__ float  g_psum[256];
__device__ float4 g_geo[1024];     // [c*16+p] = (floor(Ax), floor(Ay), wx, wy)
__device__ float  g_Wc[8192];      // [p][k][c]
__device__ float  g_We[8192];      // [p][c][k]

// ---------------- kM: per-(b,c) plane sums, one block per plane ----------------
__global__ void kM_mean(const float* __restrict__ x) {
    int bc = blockIdx.x, tid = threadIdx.x;
    const float4* p = (const float4*)(x + bc * 4096);
    float s = 0.f;
#pragma unroll
    for (int i = 0; i < 4; i++) {
        float4 v = p[tid + i * 256];
        s += v.x + v.y + v.z + v.w;
    }
    __shared__ float red[8];
    for (int o = 16; o > 0; o >>= 1) s += __shfl_down_sync(0xffffffffu, s, o);
    if ((tid & 31) == 0) red[tid >> 5] = s;
    __syncthreads();
    if (tid < 8) {
        s = red[tid];
        for (int o = 4; o > 0; o >>= 1) s += __shfl_down_sync(0xffu, s, o);
        if (tid == 0) g_psum[bc] = s;
    }
}

__device__ __forceinline__ float meta_val(int f, int p) {
    return (f == 0) ? 1.f : (f == 1) ? 0.25f
         : (f == 2) ? ((float)(p >> 2) * 0.25f - 0.375f)
                    : ((float)(p & 3) * 0.25f - 0.375f);
}

// ---------------- P2: fused meta network ----------------
__global__ void p2_meta(const float* __restrict__ Wb1, const float* __restrict__ bb1,
                        const float* __restrict__ Wb2, const float* __restrict__ bb2,
                        const float* __restrict__ Wo1, const float* __restrict__ bo1,
                        const float* __restrict__ Wo2, const float* __restrict__ bo2,
                        const float* __restrict__ Wo3, const float* __restrict__ bo3,
                        const float* __restrict__ Wr1, const float* __restrict__ br1,
                        const float* __restrict__ Wr2, const float* __restrict__ br2,
                        const float* __restrict__ Wq1, const float* __restrict__ bq1,
                        const float* __restrict__ Wq2, const float* __restrict__ bq2,
                        const float* __restrict__ Wq3, const float* __restrict__ bq3,
                        const float* __restrict__ wc,  const float* __restrict__ we) {
    __shared__ float sh[9600];
    __shared__ float s_cm[64], s_S0[64], s_S1[64], s_b1[64];
    int tid = threadIdx.x;
    if (tid < 64) {
        s_cm[tid] = (g_psum[tid] + g_psum[64 + tid] + g_psum[128 + tid] + g_psum[192 + tid])
                    * (1.0f / 16384.0f);
        s_b1[tid] = bb1[tid];
    }
    __syncthreads();
    if (tid < 64) {
        float s0 = 0.f, s1 = 0.f;
        const float* row = Wb1 + tid * 64;
#pragma unroll 8
        for (int j = 0; j < 64; j++) { float w = row[j]; s0 += w * s_cm[j]; s1 += w; }
        s_S0[tid] = s0; s_S1[tid] = s1;
    }

    if (blockIdx.x < 128) {
        // ======== offset head ========
        float* s_wo2T = sh;            // 65*64 transposed
        float* s_v1   = sh + 4160;     // 8*64
        for (int i = tid; i < 4096; i += 256)
            s_wo2T[(i & 63) * 65 + (i >> 6)] = Wo2[i];
        __syncthreads();
        int wid = tid >> 5, lane = tid & 31;
        int task = blockIdx.x * 8 + wid;   // c*16+p
        int c = task >> 4, p = task & 15;
        float e[4];
        float wba = Wb2[c * 64 + lane], wbb = Wb2[c * 64 + 32 + lane];
        float b2c = bb2[c];
#pragma unroll
        for (int f = 0; f < 4; f++) {
            float mv = meta_val(f, p);
            const float* S = (f == 0) ? s_S0 : s_S1;
            float a = fmaxf(mv * S[lane] + s_b1[lane], 0.f) * wba
                    + fmaxf(mv * S[32 + lane] + s_b1[32 + lane], 0.f) * wbb;
            for (int o = 16; o > 0; o >>= 1) a += __shfl_xor_sync(0xffffffffu, a, o);
            e[f] = fmaxf(a + b2c, 0.f);
        }
#pragma unroll
        for (int r = 0; r < 2; r++) {
            int o = lane + r * 32;
            float4 w4 = *(const float4*)&Wo1[o * 4];
            float v = bo1[o] + w4.x * e[0] + w4.y * e[1] + w4.z * e[2] + w4.w * e[3];
            s_v1[wid * 64 + o] = fmaxf(v, 0.f);
        }
        __syncwarp();
        float v2[2];
#pragma unroll
        for (int r = 0; r < 2; r++) {
            int o = lane + r * 32;
            float acc = bo2[o];
            const float* v1 = s_v1 + wid * 64;
#pragma unroll 8
            for (int f = 0; f < 64; f++) acc += s_wo2T[f * 65 + o] * v1[f];
            v2[r] = fmaxf(acc, 0.f);
        }
        float px = Wo3[lane] * v2[0] + Wo3[32 + lane] * v2[1];
        float py = Wo3[64 + lane] * v2[0] + Wo3[96 + lane] * v2[1];
        for (int o = 16; o > 0; o >>= 1) {
            px += __shfl_down_sync(0xffffffffu, px, o);
            py += __shfl_down_sync(0xffffffffu, py, o);
        }
        if (lane == 0) {
            float offx = px + bo3[0], offy = py + bo3[1];
            int ph = p >> 2, pw = p & 3;
            float Ax = ((float)pw + 0.5f) * 0.25f - 0.5f + offx;
            float Ay = ((float)ph + 0.5f) * 0.25f - 0.5f + offy;
            float fx = floorf(Ax), fy = floorf(Ay);
            g_geo[task] = make_float4(fx, fy, Ax - fx, Ay - fy);
        }
    } else {
        // ======== routing + rw + effective matrices for phase p ========
        int p = blockIdx.x - 128;
        float* s_A    = sh;            // Wb2T, later Wq2T
        float* s_B    = sh + 4160;     // Wr1T
        float* s_t1   = sh + 8320;
        float* s_emb  = sh + 8576;
        float* s_red  = sh + 8832;
        float* s_r    = sh + 9088;
        float* s_q1   = sh + 9096;
        float* s_q2   = sh + 9160;
        float* s_rw   = sh + 9224;
        for (int i = tid; i < 4096; i += 256) {
            s_A[(i & 63) * 65 + (i >> 6)] = Wb2[i];
            s_B[(i & 63) * 65 + (i >> 6)] = Wr1[i];
        }
        __syncthreads();
        {
            int f = tid >> 6, cc = tid & 63;
            float mv = meta_val(f, p);
            float S = (f == 0) ? s_S0[cc] : s_S1[cc];
            s_t1[f * 64 + cc] = fmaxf(mv * S + s_b1[cc], 0.f);
        }
        __syncthreads();
        {
            int f = tid >> 6, o = tid & 63;
            float acc = bb2[o];
            const float* t1 = s_t1 + f * 64;
#pragma unroll 8
            for (int cc = 0; cc < 64; cc++) acc += s_A[cc * 65 + o] * t1[cc];
            s_emb[f * 64 + o] = fmaxf(acc, 0.f);
        }
        __syncthreads();
        for (int i = tid; i < 4096; i += 256)
            s_A[(i & 63) * 65 + (i >> 6)] = Wq2[i];
        {
            int f = tid >> 6, o = tid & 63;
            float acc = br1[o];
            const float* em = s_emb + f * 64;
#pragma unroll 8
            for (int c = 0; c < 64; c++) acc += s_B[c * 65 + o] * em[c];
            s_red[tid] = fmaxf(acc, 0.f) * Wr2[o];
        }
        __syncthreads();
        if (tid < 4) {
            float v = br2[0];
            for (int o = 0; o < 64; o++) v += s_red[tid * 64 + o];
            s_r[tid] = 1.f / (1.f + expf(-v));
        }
        __syncthreads();
        if (tid < 64) {
            float4 w4 = *(const float4*)&Wq1[tid * 4];
            float acc = bq1[tid] + w4.x * s_r[0] + w4.y * s_r[1] + w4.z * s_r[2] + w4.w * s_r[3];
            s_q1[tid] = fmaxf(acc, 0.f);
        }
        __syncthreads();
        if (tid < 64) {
            float acc = bq2[tid];
#pragma unroll 8
            for (int f = 0; f < 64; f++) acc += s_A[f * 65 + tid] * s_q1[f];
            s_q2[tid] = fmaxf(acc, 0.f);
        }
        __syncthreads();
        if (tid < 4) {
            float acc = bq3[tid];
            const float* wr = Wq3 + tid * 64;
#pragma unroll 8
            for (int f = 0; f < 64; f++) acc += wr[f] * s_q2[f];
            s_rw[tid] = 1.f / (1.f + expf(-acc));
        }
        __syncthreads();
        float rw0 = s_rw[0], rw1 = s_rw[1], rw2 = s_rw[2], rw3 = s_rw[3];
        for (int rem = tid; rem < 512; rem += 256) {
            float a = rw0 * wc[rem]        + rw1 * wc[512 + rem]
                    + rw2 * wc[1024 + rem] + rw3 * wc[1536 + rem];
            float b2 = rw0 * we[rem]        + rw1 * we[512 + rem]
                     + rw2 * we[1024 + rem] + rw3 * we[1536 + rem];
            g_Wc[p * 512 + rem] = a;
            g_We[p * 512 + rem] = b2;
        }
    }
}

// ---------------- K4: main per-pixel kernel (register-resident fea) ----------------
__global__ void __launch_bounds__(256, 2)
k4_main(const float* __restrict__ x, float* __restrict__ out) {
    extern __shared__ float sm[];
    float4* s_geo = (float4*)sm;                 // 1024 floats
    float*  s_Wc  = sm + 1024;                   // 4*516
    float*  s_We  = sm + 3088;                   // 4*516
    float*  s_out = sm + 5152;                   // 16*280
    int tid = threadIdx.x;
    int b = blockIdx.x >> 8, ho = blockIdx.x & 255;
    int mh = ho >> 2, ph = ho & 3;

    { int c = tid >> 2, pwl = tid & 3; s_geo[tid] = g_geo[c * 16 + ph * 4 + pwl]; }
    for (int i = tid; i < 2048; i += 256) {
        int pwl = i >> 9, rem = i & 511;
        s_Wc[pwl * 516 + rem] = g_Wc[(ph * 4 + pwl) * 512 + rem];
        s_We[pwl * 516 + rem] = g_We[(ph * 4 + pwl) * 512 + rem];
    }
    __syncthreads();

    // ---- gather into registers: pw warp-uniform; pixel w = 4*mw + pwg ----
    int pwg = tid >> 6, mw = tid & 63;
    const float* xb = x + b * 262144;
    float fea[64];
#pragma unroll
    for (int c = 0; c < 64; c++) {
        float4 geo = s_geo[c * 4 + pwg];          // warp-uniform broadcast
        int x0 = mw + (int)geo.x;
        int y0 = mh + (int)geo.y;
        float wx = geo.z, wy = geo.w;
        int cx0 = min(max(x0, 0), 63),     cx1 = min(max(x0 + 1, 0), 63);
        int cy0 = min(max(y0, 0), 63),     cy1 = min(max(y0 + 1, 0), 63);
        float mx0 = ((unsigned)x0       < 64u) ? 1.f : 0.f;
        float mx1 = ((unsigned)(x0 + 1) < 64u) ? 1.f : 0.f;
        float my0 = ((unsigned)y0       < 64u) ? 1.f : 0.f;
        float my1 = ((unsigned)(y0 + 1) < 64u) ? 1.f : 0.f;
        const float* pl = xb + c * 4096;
        float v00 = pl[cy0 * 64 + cx0] * (my0 * mx0);
        float v01 = pl[cy0 * 64 + cx1] * (my0 * mx1);
        float v10 = pl[cy1 * 64 + cx0] * (my1 * mx0);
        float v11 = pl[cy1 * 64 + cx1] * (my1 * mx1);
        float top = v00 + wx * (v01 - v00);
        float bot = v10 + wx * (v11 - v10);
        fea[c] = top + wy * (bot - top);
    }

    // ---- mix ----
    const float* Wcp = s_Wc + pwg * 516;
    const float* Wep = s_We + pwg * 516;
    float mid[8];
#pragma unroll
    for (int kk = 0; kk < 8; kk++) mid[kk] = 0.f;
#pragma unroll
    for (int c4 = 0; c4 < 16; c4++) {
#pragma unroll
        for (int kk = 0; kk < 8; kk++) {
            float4 w4 = *(const float4*)&Wcp[kk * 64 + 4 * c4];
            mid[kk] += fea[4*c4] * w4.x + fea[4*c4+1] * w4.y
                     + fea[4*c4+2] * w4.z + fea[4*c4+3] * w4.w;
        }
    }

    // ---- expand + chunked smem transpose -> coalesced STG ----
    int gw = tid + 8 * (tid >> 6);                 // write skew
    int rr = (tid & 3) * 64 + (tid >> 2);          // storage row of pixel w=tid
    int gr = rr + 8 * (rr >> 6);                   // read skew
    float* ob0 = out + (b * 64 * 256 + ho) * 256 + tid;
#pragma unroll
    for (int chk = 0; chk < 4; chk++) {
        float ovals[16];
#pragma unroll
        for (int j = 0; j < 16; j++) {
            int c = chk * 16 + j;
            float4 wa = *(const float4*)&Wep[c * 8];
            float4 wb = *(const float4*)&Wep[c * 8 + 4];
            ovals[j] = fea[c]
                + wa.x * mid[0] + wa.y * mid[1] + wa.z * mid[2] + wa.w * mid[3]
                + wb.x * mid[4] + wb.y * mid[5] + wb.z * mid[6] + wb.w * mid[7];
        }
        __syncthreads();   // previous chunk's reads complete
#pragma unroll
        for (int cc = 0; cc < 16; cc++) s_out[cc * 280 + gw] = ovals[cc];
        __syncthreads();
        float* ob = ob0 + chk * 16 * 65536;
#pragma unroll
        for (int cc = 0; cc < 16; cc++) ob[cc * 65536] = s_out[cc * 280 + gr];
    }
}

extern "C" void kernel_launch(void* const* d_in, const int* in_sizes, int n_in,
                              void* d_out, int out_size) {
    const float* x   = (const float*)d_in[0];
    const float* wc  = (const float*)d_in[1];
    const float* we  = (const float*)d_in[2];
    const float* Wb1 = (const float*)d_in[3];
    const float* bb1 = (const float*)d_in[4];
    const float* Wb2 = (const float*)d_in[5];
    const float* bb2 = (const float*)d_in[6];
    const float* Wr1 = (const float*)d_in[7];
    const float* br1 = (const float*)d_in[8];
    const float* Wr2 = (const float*)d_in[9];
    const float* br2 = (const float*)d_in[10];
    const float* Wq1 = (const float*)d_in[11];
    const float* bq1 = (const float*)d_in[12];
    const float* Wq2 = (const float*)d_in[13];
    const float* bq2 = (const float*)d_in[14];
    const float* Wq3 = (const float*)d_in[15];
    const float* bq3 = (const float*)d_in[16];
    const float* Wo1 = (const float*)d_in[17];
    const float* bo1 = (const float*)d_in[18];
    const float* Wo2 = (const float*)d_in[19];
    const float* bo2 = (const float*)d_in[20];
    const float* Wo3 = (const float*)d_in[21];
    const float* bo3 = (const float*)d_in[22];
    float* out = (float*)d_out;

    cudaFuncSetAttribute(k4_main, cudaFuncAttributeMaxDynamicSharedMemorySize, 9632 * 4);

    kM_mean<<<256, 256>>>(x);
    p2_meta<<<144, 256>>>(Wb1, bb1, Wb2, bb2, Wo1, bo1, Wo2, bo2, Wo3, bo3,
                          Wr1, br1, Wr2, br2, Wq1, bq1, Wq2, bq2, Wq3, bq3, wc, we);
    k4_main<<<1024, 256, 9632 * 4>>>(x, out);
}

// round 12
// speedup vs baseline: 2.2014x; 1.0242x over previous
#include <cuda_runtime.h>
#include <math.h>

__device__ float  g_psum[1024];
__device__ float4 g_geo[1024];     // [c*16+p] = (floor(Ax), floor(Ay), wx, wy)
__device__ float  g_Wc[8192];      // [p][k][c]
__device__ float  g_We[8192];      // [p][k][c]  (transposed!)

typedef unsigned long long ull;
__device__ __forceinline__ ull pk2(float lo, float hi) {
    ull r; asm("mov.b64 %0, {%1,%2};" : "=l"(r) : "f"(lo), "f"(hi)); return r;
}
__device__ __forceinline__ void upk2(ull v, float& lo, float& hi) {
    asm("mov.b64 {%0,%1}, %2;" : "=f"(lo), "=f"(hi) : "l"(v));
}
__device__ __forceinline__ ull ffma2(ull a, ull b, ull c) {
    ull d; asm("fma.rn.f32x2 %0, %1, %2, %3;" : "=l"(d) : "l"(a), "l"(b), "l"(c)); return d;
}

// ---------------- kM: quarter-plane sums, 1024 blocks x 128 thr ----------------
__global__ void kM_mean(const float* __restrict__ x) {
    int blk = blockIdx.x, tid = threadIdx.x;
    const float4* p = (const float4*)(x + blk * 1024);
    float4 a = p[tid], b = p[tid + 128];
    float s = a.x + a.y + a.z + a.w + b.x + b.y + b.z + b.w;
    __shared__ float red[4];
    for (int o = 16; o > 0; o >>= 1) s += __shfl_down_sync(0xffffffffu, s, o);
    if ((tid & 31) == 0) red[tid >> 5] = s;
    __syncthreads();
    if (tid == 0) g_psum[blk] = red[0] + red[1] + red[2] + red[3];
}

__device__ __forceinline__ float meta_val(int f, int p) {
    return (f == 0) ? 1.f : (f == 1) ? 0.25f
         : (f == 2) ? ((float)(p >> 2) * 0.25f - 0.375f)
                    : ((float)(p & 3) * 0.25f - 0.375f);
}

// ---------------- P2: fused meta network ----------------
__global__ void p2_meta(const float* __restrict__ Wb1, const float* __restrict__ bb1,
                        const float* __restrict__ Wb2, const float* __restrict__ bb2,
                        const float* __restrict__ Wo1, const float* __restrict__ bo1,
                        const float* __restrict__ Wo2, const float* __restrict__ bo2,
                        const float* __restrict__ Wo3, const float* __restrict__ bo3,
                        const float* __restrict__ Wr1, const float* __restrict__ br1,
                        const float* __restrict__ Wr2, const float* __restrict__ br2,
                        const float* __restrict__ Wq1, const float* __restrict__ bq1,
                        const float* __restrict__ Wq2, const float* __restrict__ bq2,
                        const float* __restrict__ Wq3, const float* __restrict__ bq3,
                        const float* __restrict__ wc,  const float* __restrict__ we) {
    __shared__ float sh[9600];
    __shared__ float s_cm[64], s_S0[64], s_S1[64], s_b1[64];
    int tid = threadIdx.x;
    if (tid < 64) {
        float s = 0.f;
#pragma unroll
        for (int b2 = 0; b2 < 4; b2++)
#pragma unroll
            for (int q = 0; q < 4; q++) s += g_psum[b2 * 256 + tid * 4 + q];
        s_cm[tid] = s * (1.0f / 16384.0f);
        s_b1[tid] = bb1[tid];
    }
    __syncthreads();
    if (tid < 64) {
        float s0 = 0.f, s1 = 0.f;
        const float* row = Wb1 + tid * 64;
#pragma unroll 8
        for (int j = 0; j < 64; j++) { float w = row[j]; s0 += w * s_cm[j]; s1 += w; }
        s_S0[tid] = s0; s_S1[tid] = s1;
    }

    if (blockIdx.x < 128) {
        // ======== offset head ========
        float* s_wo2T = sh;            // 65*64 transposed
        float* s_v1   = sh + 4160;     // 8*64
        for (int i = tid; i < 4096; i += 256)
            s_wo2T[(i & 63) * 65 + (i >> 6)] = Wo2[i];
        __syncthreads();
        int wid = tid >> 5, lane = tid & 31;
        int task = blockIdx.x * 8 + wid;   // c*16+p
        int c = task >> 4, p = task & 15;
        float e[4];
        float wba = Wb2[c * 64 + lane], wbb = Wb2[c * 64 + 32 + lane];
        float b2c = bb2[c];
#pragma unroll
        for (int f = 0; f < 4; f++) {
            float mv = meta_val(f, p);
            const float* S = (f == 0) ? s_S0 : s_S1;
            float a = fmaxf(mv * S[lane] + s_b1[lane], 0.f) * wba
                    + fmaxf(mv * S[32 + lane] + s_b1[32 + lane], 0.f) * wbb;
            for (int o = 16; o > 0; o >>= 1) a += __shfl_xor_sync(0xffffffffu, a, o);
            e[f] = fmaxf(a + b2c, 0.f);
        }
#pragma unroll
        for (int r = 0; r < 2; r++) {
            int o = lane + r * 32;
            float4 w4 = *(const float4*)&Wo1[o * 4];
            float v = bo1[o] + w4.x * e[0] + w4.y * e[1] + w4.z * e[2] + w4.w * e[3];
            s_v1[wid * 64 + o] = fmaxf(v, 0.f);
        }
        __syncwarp();
        float v2[2];
#pragma unroll
        for (int r = 0; r < 2; r++) {
            int o = lane + r * 32;
            float acc = bo2[o];
            const float* v1 = s_v1 + wid * 64;
#pragma unroll 8
            for (int f = 0; f < 64; f++) acc += s_wo2T[f * 65 + o] * v1[f];
            v2[r] = fmaxf(acc, 0.f);
        }
        float px = Wo3[lane] * v2[0] + Wo3[32 + lane] * v2[1];
        float py = Wo3[64 + lane] * v2[0] + Wo3[96 + lane] * v2[1];
        for (int o = 16; o > 0; o >>= 1) {
            px += __shfl_down_sync(0xffffffffu, px, o);
            py += __shfl_down_sync(0xffffffffu, py, o);
        }
        if (lane == 0) {
            float offx = px + bo3[0], offy = py + bo3[1];
            int ph = p >> 2, pw = p & 3;
            float Ax = ((float)pw + 0.5f) * 0.25f - 0.5f + offx;
            float Ay = ((float)ph + 0.5f) * 0.25f - 0.5f + offy;
            float fx = floorf(Ax), fy = floorf(Ay);
            g_geo[task] = make_float4(fx, fy, Ax - fx, Ay - fy);
        }
    } else {
        // ======== routing + rw + effective matrices for phase p ========
        int p = blockIdx.x - 128;
        float* s_A    = sh;            // Wb2T, later Wq2T
        float* s_B    = sh + 4160;     // Wr1T
        float* s_t1   = sh + 8320;
        float* s_emb  = sh + 8576;
        float* s_red  = sh + 8832;
        float* s_r    = sh + 9088;
        float* s_q1   = sh + 9096;
        float* s_q2   = sh + 9160;
        float* s_rw   = sh + 9224;
        for (int i = tid; i < 4096; i += 256) {
            s_A[(i & 63) * 65 + (i >> 6)] = Wb2[i];
            s_B[(i & 63) * 65 + (i >> 6)] = Wr1[i];
        }
        __syncthreads();
        {
            int f = tid >> 6, cc = tid & 63;
            float mv = meta_val(f, p);
            float S = (f == 0) ? s_S0[cc] : s_S1[cc];
            s_t1[f * 64 + cc] = fmaxf(mv * S + s_b1[cc], 0.f);
        }
        __syncthreads();
        {
            int f = tid >> 6, o = tid & 63;
            float acc = bb2[o];
            const float* t1 = s_t1 + f * 64;
#pragma unroll 8
            for (int cc = 0; cc < 64; cc++) acc += s_A[cc * 65 + o] * t1[cc];
            s_emb[f * 64 + o] = fmaxf(acc, 0.f);
        }
        __syncthreads();
        for (int i = tid; i < 4096; i += 256)
            s_A[(i & 63) * 65 + (i >> 6)] = Wq2[i];
        {
            int f = tid >> 6, o = tid & 63;
            float acc = br1[o];
            const float* em = s_emb + f * 64;
#pragma unroll 8
            for (int c = 0; c < 64; c++) acc += s_B[c * 65 + o] * em[c];
            s_red[tid] = fmaxf(acc, 0.f) * Wr2[o];
        }
        __syncthreads();
        if (tid < 4) {
            float v = br2[0];
            for (int o = 0; o < 64; o++) v += s_red[tid * 64 + o];
            s_r[tid] = 1.f / (1.f + expf(-v));
        }
        __syncthreads();
        if (tid < 64) {
            float4 w4 = *(const float4*)&Wq1[tid * 4];
            float acc = bq1[tid] + w4.x * s_r[0] + w4.y * s_r[1] + w4.z * s_r[2] + w4.w * s_r[3];
            s_q1[tid] = fmaxf(acc, 0.f);
        }
        __syncthreads();
        if (tid < 64) {
            float acc = bq2[tid];
#pragma unroll 8
            for (int f = 0; f < 64; f++) acc += s_A[f * 65 + tid] * s_q1[f];
            s_q2[tid] = fmaxf(acc, 0.f);
        }
        __syncthreads();
        if (tid < 4) {
            float acc = bq3[tid];
            const float* wr = Wq3 + tid * 64;
#pragma unroll 8
            for (int f = 0; f < 64; f++) acc += wr[f] * s_q2[f];
            s_rw[tid] = 1.f / (1.f + expf(-acc));
        }
        __syncthreads();
        float rw0 = s_rw[0], rw1 = s_rw[1], rw2 = s_rw[2], rw3 = s_rw[3];
        for (int rem = tid; rem < 512; rem += 256) {
            // g_Wc layout [k][c]: rem = k*64+c matches wc[e][k][c] directly
            float a = rw0 * wc[rem]        + rw1 * wc[512 + rem]
                    + rw2 * wc[1024 + rem] + rw3 * wc[1536 + rem];
            g_Wc[p * 512 + rem] = a;
            // g_We layout [k][c] from we[e][c][k]
            int k = rem >> 6, c = rem & 63;
            int widx = c * 8 + k;
            float b2 = rw0 * we[widx]        + rw1 * we[512 + widx]
                     + rw2 * we[1024 + widx] + rw3 * we[1536 + widx];
            g_We[p * 512 + rem] = b2;
        }
    }
}

// ---------------- K4: main per-pixel kernel ----------------
__global__ void __launch_bounds__(256, 2)
k4_main(const float* __restrict__ x, float* __restrict__ out) {
    extern __shared__ float sm[];
    float4* s_geo = (float4*)sm;                 // 1024 floats
    float*  s_Wc  = sm + 1024;                   // 4*516
    float*  s_We  = sm + 3088;                   // 4*516
    float*  s_out = sm + 5152;                   // 16*280
    int tid = threadIdx.x;
    int b = blockIdx.x >> 8, ho = blockIdx.x & 255;
    int mh = ho >> 2, ph = ho & 3;

    { int c = tid >> 2, pwl = tid & 3; s_geo[tid] = g_geo[c * 16 + ph * 4 + pwl]; }
    for (int i = tid; i < 2048; i += 256) {
        int pwl = i >> 9, rem = i & 511;
        s_Wc[pwl * 516 + rem] = g_Wc[(ph * 4 + pwl) * 512 + rem];
        s_We[pwl * 516 + rem] = g_We[(ph * 4 + pwl) * 512 + rem];
    }
    __syncthreads();

    // ---- gather into registers: pw warp-uniform; pixel w = 4*mw + pwg ----
    int pwg = tid >> 6, mw = tid & 63;
    const float* xb = x + b * 262144;
    float fea[64];
#pragma unroll
    for (int c = 0; c < 64; c++) {
        float4 geo = s_geo[c * 4 + pwg];          // warp-uniform broadcast
        int x0 = mw + (int)geo.x;
        int y0 = mh + (int)geo.y;
        float wx = geo.z, wy = geo.w;
        int cx0 = min(max(x0, 0), 63),     cx1 = min(max(x0 + 1, 0), 63);
        int cy0 = min(max(y0, 0), 63),     cy1 = min(max(y0 + 1, 0), 63);
        bool okx0 = (unsigned)x0 < 64u,  okx1 = (unsigned)(x0 + 1) < 64u;
        bool oky0 = (unsigned)y0 < 64u,  oky1 = (unsigned)(y0 + 1) < 64u;
        const float* pl = xb + c * 4096;
        float t00 = pl[cy0 * 64 + cx0], t01 = pl[cy0 * 64 + cx1];
        float t10 = pl[cy1 * 64 + cx0], t11 = pl[cy1 * 64 + cx1];
        float v00 = (oky0 && okx0) ? t00 : 0.f;
        float v01 = (oky0 && okx1) ? t01 : 0.f;
        float v10 = (oky1 && okx0) ? t10 : 0.f;
        float v11 = (oky1 && okx1) ? t11 : 0.f;
        float top = v00 + wx * (v01 - v00);
        float bot = v10 + wx * (v11 - v10);
        fea[c] = top + wy * (bot - top);
    }

    // ---- mix (packed f32x2, acc pairs over channels) ----
    const float* Wcp = s_Wc + pwg * 516;
    const float* Wep = s_We + pwg * 516;
    ull acc2[8];
#pragma unroll
    for (int kk = 0; kk < 8; kk++) acc2[kk] = 0ull;
#pragma unroll
    for (int c4 = 0; c4 < 16; c4++) {
        ull fa = pk2(fea[4 * c4],     fea[4 * c4 + 1]);
        ull fb = pk2(fea[4 * c4 + 2], fea[4 * c4 + 3]);
#pragma unroll
        for (int kk = 0; kk < 8; kk++) {
            ulonglong2 w2 = *(const ulonglong2*)&Wcp[kk * 64 + 4 * c4];
            acc2[kk] = ffma2(w2.x, fa, acc2[kk]);
            acc2[kk] = ffma2(w2.y, fb, acc2[kk]);
        }
    }
    ull midb[8];
#pragma unroll
    for (int kk = 0; kk < 8; kk++) {
        float lo, hi; upk2(acc2[kk], lo, hi);
        float m = lo + hi;
        midb[kk] = pk2(m, m);
    }

    // ---- expand (packed, mid broadcasts) + chunked smem transpose -> coalesced STG ----
    int gw = tid + 8 * (tid >> 6);                 // write skew
    int rr = (tid & 3) * 64 + (tid >> 2);          // storage row of pixel w=tid
    int gr = rr + 8 * (rr >> 6);                   // read skew
    float* ob0 = out + (b * 64 * 256 + ho) * 256 + tid;
#pragma unroll
    for (int chk = 0; chk < 4; chk++) {
        float ovals[16];
#pragma unroll
        for (int j4 = 0; j4 < 4; j4++) {
            int cb = chk * 16 + j4 * 4;
            ull a0 = pk2(fea[cb],     fea[cb + 1]);
            ull a1 = pk2(fea[cb + 2], fea[cb + 3]);
#pragma unroll
            for (int k = 0; k < 8; k++) {
                ulonglong2 w2 = *(const ulonglong2*)&Wep[k * 64 + cb];
                a0 = ffma2(w2.x, midb[k], a0);
                a1 = ffma2(w2.y, midb[k], a1);
            }
            upk2(a0, ovals[j4 * 4],     ovals[j4 * 4 + 1]);
            upk2(a1, ovals[j4 * 4 + 2], ovals[j4 * 4 + 3]);
        }
        __syncthreads();   // previous chunk's reads complete
#pragma unroll
        for (int cc = 0; cc < 16; cc++) s_out[cc * 280 + gw] = ovals[cc];
        __syncthreads();
        float* ob = ob0 + chk * 16 * 65536;
#pragma unroll
        for (int cc = 0; cc < 16; cc++) ob[cc * 65536] = s_out[cc * 280 + gr];
    }
}

extern "C" void kernel_launch(void* const* d_in, const int* in_sizes, int n_in,
                              void* d_out, int out_size) {
    const float* x   = (const float*)d_in[0];
    const float* wc  = (const float*)d_in[1];
    const float* we  = (const float*)d_in[2];
    const float* Wb1 = (const float*)d_in[3];
    const float* bb1 = (const float*)d_in[4];
    const float* Wb2 = (const float*)d_in[5];
    const float* bb2 = (const float*)d_in[6];
    const float* Wr1 = (const float*)d_in[7];
    const float* br1 = (const float*)d_in[8];
    const float* Wr2 = (const float*)d_in[9];
    const float* br2 = (const float*)d_in[10];
    const float* Wq1 = (const float*)d_in[11];
    const float* bq1 = (const float*)d_in[12];
    const float* Wq2 = (const float*)d_in[13];
    const float* bq2 = (const float*)d_in[14];
    const float* Wq3 = (const float*)d_in[15];
    const float* bq3 = (const float*)d_in[16];
    const float* Wo1 = (const float*)d_in[17];
    const float* bo1 = (const float*)d_in[18];
    const float* Wo2 = (const float*)d_in[19];
    const float* bo2 = (const float*)d_in[20];
    const float* Wo3 = (const float*)d_in[21];
    const float* bo3 = (const float*)d_in[22];
    float* out = (float*)d_out;

    cudaFuncSetAttribute(k4_main, cudaFuncAttributeMaxDynamicSharedMemorySize, 9632 * 4);

    kM_mean<<<1024, 128>>>(x);
    p2_meta<<<144, 256>>>(Wb1, bb1, Wb2, bb2, Wo1, bo1, Wo2, bo2, Wo3, bo3,
                          Wr1, br1, Wr2, br2, Wq1, bq1, Wq2, bq2, Wq3, bq3, wc, we);
    k4_main<<<1024, 256, 9632 * 4>>>(x, out);
}